// round 3
// baseline (speedup 1.0000x reference)
#include <cuda_runtime.h>
#include <cuda_bf16.h>
#include <cstdint>

// Problem constants
#define BB 8
#define TT 128
#define SS 512
#define DD 128

// Scratch (allocation-free rule: __device__ globals)
__device__ float g_HU[BB * SS * DD];   // H @ Ua, [B,S,D]
__device__ float g_XG[BB * TT * 512];  // x@W + bias for 4 gates (i,f,c,o), [B,T,512]

__device__ __forceinline__ float tanh_ap(float x) {
    float y;
    asm("tanh.approx.f32 %0, %1;" : "=f"(y) : "f"(x));
    return y;
}

__device__ __forceinline__ float4 ldg4(const float* p) {
    return __ldg(reinterpret_cast<const float4*>(p));
}

// ---------------------------------------------------------------------------
// Precompute HU[b,s,e] = sum_d H[b,s,d] * Ua[d,e]
// grid 512, block 128; each block does 8 rows of the flattened 4096-row matrix
// ---------------------------------------------------------------------------
__global__ void hu_kernel(const float* __restrict__ H, const float* __restrict__ Ua) {
    __shared__ __align__(16) float sH[8][DD];
    const int tid = threadIdx.x;          // 0..127 = output column e
    const int row0 = blockIdx.x * 8;
    #pragma unroll
    for (int r = 0; r < 8; r++) sH[r][tid] = H[(row0 + r) * DD + tid];
    __syncthreads();

    float acc[8];
    #pragma unroll
    for (int r = 0; r < 8; r++) acc[r] = 0.f;

    #pragma unroll 4
    for (int k = 0; k < DD; k++) {
        float ua = __ldg(Ua + k * DD + tid);
        #pragma unroll
        for (int r = 0; r < 8; r++) acc[r] += sH[r][k] * ua;
    }
    #pragma unroll
    for (int r = 0; r < 8; r++) g_HU[(row0 + r) * DD + tid] = acc[r];
}

// ---------------------------------------------------------------------------
// Precompute XG[row, g*128+jj] = b_g[jj] + sum_k x[row,k] * W_g[k,jj]
// rows = B*T = 1024.  grid 128, block 512; each block does 8 rows.
// Gate order: i, f, c, o.
// ---------------------------------------------------------------------------
__global__ void xw_kernel(const float* __restrict__ x,
                          const float* __restrict__ Wi, const float* __restrict__ Wf,
                          const float* __restrict__ Wc, const float* __restrict__ Wo,
                          const float* __restrict__ bi, const float* __restrict__ bf,
                          const float* __restrict__ bc, const float* __restrict__ bo) {
    __shared__ __align__(16) float sx[8][DD];
    const int tid = threadIdx.x;          // 0..511
    const int row0 = blockIdx.x * 8;

    for (int i = tid; i < 8 * DD; i += 512)
        sx[i >> 7][i & 127] = x[row0 * DD + i];
    __syncthreads();

    const int g  = tid >> 7;
    const int jj = tid & 127;
    const float* W  = (g == 0) ? Wi : (g == 1) ? Wf : (g == 2) ? Wc : Wo;
    const float* bb = (g == 0) ? bi : (g == 1) ? bf : (g == 2) ? bc : bo;

    float acc[8];
    const float bias = __ldg(bb + jj);
    #pragma unroll
    for (int r = 0; r < 8; r++) acc[r] = bias;

    #pragma unroll 4
    for (int k = 0; k < DD; k++) {
        float w = __ldg(W + k * DD + jj);
        #pragma unroll
        for (int r = 0; r < 8; r++) acc[r] += sx[r][k] * w;
    }
    #pragma unroll
    for (int r = 0; r < 8; r++) g_XG[(row0 + r) * 512 + tid] = acc[r];
}

// ---------------------------------------------------------------------------
// Persistent recurrent kernel: one CTA per batch, 1024 threads, T=128 steps.
// ---------------------------------------------------------------------------
__global__ __launch_bounds__(1024, 1)
void rec_kernel(const float* __restrict__ H, const float* __restrict__ init,
                const float* __restrict__ Wa, const float* __restrict__ v,
                const float* __restrict__ Ui, const float* __restrict__ Ci,
                const float* __restrict__ Uf, const float* __restrict__ Cf,
                const float* __restrict__ Uc, const float* __restrict__ Cc,
                const float* __restrict__ Uo, const float* __restrict__ Co,
                float* __restrict__ out) {
    const int b    = blockIdx.x;
    const int tid  = threadIdx.x;
    const int lane = tid & 31;
    const int wp   = tid >> 5;

    __shared__ __align__(16) float sh[DD];      // h state
    __shared__ __align__(16) float scell[DD];   // c state
    __shared__ __align__(16) float sq[DD];      // q = h@Wa
    __shared__ __align__(16) float sv[DD];      // v
    __shared__ __align__(16) float sctx[DD];    // context
    __shared__ __align__(16) float sscore[SS];  // scores -> exp values
    __shared__ __align__(16) float part32[32][DD]; // partials for q and ctx
    __shared__ __align__(16) float gpart[8][512];  // gate partials
    __shared__ __align__(16) float gact[512];      // activated gates
    __shared__ float red[32];
    __shared__ float smax, szinv;

    if (tid < DD) {
        sh[tid]    = init[b * DD + tid];             // init_states[0][b]
        scell[tid] = init[BB * DD + b * DD + tid];   // init_states[1][b]
        sv[tid]    = v[tid];
    }
    __syncthreads();

    const float* Hb  = H    + b * SS * DD;
    const float* HUb = g_HU + b * SS * DD;
    const float* XGb = g_XG + b * TT * 512;

    // Per-thread constants for the gate phase:
    // thread = (r, jq): r = k-chunk [16r,16r+16), jq -> output cols [4jq,4jq+4)
    const int gr  = tid >> 7;            // 0..7
    const int gjq = tid & 127;           // 0..127
    const int gg  = gjq >> 5;            // gate id (uniform per warp)
    const int gjj = (gjq & 31) * 4;      // within-gate column (float4 base)
    const float* Ug = (gg == 0) ? Ui : (gg == 1) ? Uf : (gg == 2) ? Uc : Uo;
    const float* Cg = (gg == 0) ? Ci : (gg == 1) ? Cf : (gg == 2) ? Cc : Co;

    for (int t = 0; t < TT; t++) {
        // ---------- Phase 1: q = h @ Wa ----------
        {
            const int r  = wp;        // k-chunk [4r, 4r+4)
            const int dq = lane;      // output float4 group
            float4 acc = make_float4(0.f, 0.f, 0.f, 0.f);
            #pragma unroll
            for (int kk = 0; kk < 4; kk++) {
                const int k = r * 4 + kk;
                const float hk = sh[k];
                float4 w = ldg4(Wa + k * DD + dq * 4);
                acc.x += hk * w.x; acc.y += hk * w.y;
                acc.z += hk * w.z; acc.w += hk * w.w;
            }
            *reinterpret_cast<float4*>(&part32[r][dq * 4]) = acc;
        }
        __syncthreads();
        if (tid < DD) {
            float s = 0.f;
            #pragma unroll
            for (int r = 0; r < 32; r++) s += part32[r][tid];
            sq[tid] = s;
        }
        __syncthreads();

        // ---------- Phase 2: scores[s] = v . tanh(HU[s] + q) ----------
        {
            const float4 q4 = *reinterpret_cast<const float4*>(&sq[lane * 4]);
            const float4 vv = *reinterpret_cast<const float4*>(&sv[lane * 4]);
            #pragma unroll 4
            for (int i = 0; i < 16; i++) {
                const int s = wp + (i << 5);
                float4 hu = ldg4(HUb + s * DD + lane * 4);
                float val = tanh_ap(hu.x + q4.x) * vv.x
                          + tanh_ap(hu.y + q4.y) * vv.y
                          + tanh_ap(hu.z + q4.z) * vv.z
                          + tanh_ap(hu.w + q4.w) * vv.w;
                #pragma unroll
                for (int o = 16; o > 0; o >>= 1)
                    val += __shfl_xor_sync(0xffffffffu, val, o);
                if (lane == 0) sscore[s] = val;
            }
        }
        __syncthreads();

        // ---------- Phase 3: softmax stats (max, then exp + sum) ----------
        {
            float m = -1e30f;
            if (tid < SS) m = sscore[tid];
            #pragma unroll
            for (int o = 16; o > 0; o >>= 1)
                m = fmaxf(m, __shfl_xor_sync(0xffffffffu, m, o));
            if (lane == 0) red[wp] = m;
        }
        __syncthreads();
        if (tid == 0) {
            float mm = -1e30f;
            #pragma unroll
            for (int i = 0; i < 16; i++) mm = fmaxf(mm, red[i]);
            smax = mm;
        }
        __syncthreads();
        {
            float zs = 0.f;
            if (tid < SS) {
                float e = __expf(sscore[tid] - smax);
                sscore[tid] = e;
                zs = e;
            }
            #pragma unroll
            for (int o = 16; o > 0; o >>= 1)
                zs += __shfl_xor_sync(0xffffffffu, zs, o);
            if (lane == 0) red[wp] = zs;
        }
        __syncthreads();
        if (tid == 0) {
            float z = 0.f;
            #pragma unroll
            for (int i = 0; i < 16; i++) z += red[i];
            szinv = 1.f / z;
        }
        __syncthreads();

        // ---------- Phase 4: context[d] = (sum_s e[s] * H[s,d]) * (1/Z) ----------
        {
            const int r  = wp;        // s-chunk [16r, 16r+16)
            const int dq = lane;      // d float4 group
            float4 acc = make_float4(0.f, 0.f, 0.f, 0.f);
            #pragma unroll 4
            for (int j = 0; j < 16; j++) {
                const int s = r * 16 + j;
                const float e = sscore[s];
                float4 h4 = ldg4(Hb + s * DD + dq * 4);
                acc.x += e * h4.x; acc.y += e * h4.y;
                acc.z += e * h4.z; acc.w += e * h4.w;
            }
            *reinterpret_cast<float4*>(&part32[r][dq * 4]) = acc;
        }
        __syncthreads();
        if (tid < DD) {
            float s = 0.f;
            #pragma unroll
            for (int r = 0; r < 32; r++) s += part32[r][tid];
            sctx[tid] = s * szinv;
        }
        __syncthreads();

        // ---------- Phase 5: gates = XG[t] + h@U + ctx@C ----------
        {
            float4 acc = make_float4(0.f, 0.f, 0.f, 0.f);
            #pragma unroll 4
            for (int kk = 0; kk < 16; kk++) {
                const int k = gr * 16 + kk;
                const float hk = sh[k];
                const float ck = sctx[k];
                float4 u = ldg4(Ug + k * DD + gjj);
                float4 c = ldg4(Cg + k * DD + gjj);
                acc.x += hk * u.x + ck * c.x;
                acc.y += hk * u.y + ck * c.y;
                acc.z += hk * u.z + ck * c.z;
                acc.w += hk * u.w + ck * c.w;
            }
            *reinterpret_cast<float4*>(&gpart[gr][gjq * 4]) = acc;
        }
        __syncthreads();
        if (tid < 512) {
            float pre = XGb[t * 512 + tid];
            #pragma unroll
            for (int r = 0; r < 8; r++) pre += gpart[r][tid];
            const int g = tid >> 7;
            gact[tid] = (g == 2) ? tanhf(pre) : 1.f / (1.f + __expf(-pre));
        }
        __syncthreads();

        // ---------- Phase 6: LSTM state update + output ----------
        if (tid < DD) {
            const float i_g = gact[tid];
            const float f_g = gact[128 + tid];
            const float g_w = gact[256 + tid];
            const float o_g = gact[384 + tid];
            const float c_new = f_g * scell[tid] + i_g * g_w;
            const float h_new = o_g * tanhf(c_new);
            scell[tid] = c_new;
            sh[tid]    = h_new;
            out[(b * TT + t) * DD + tid] = h_new;
        }
        __syncthreads();
    }
}

// ---------------------------------------------------------------------------
extern "C" void kernel_launch(void* const* d_in, const int* in_sizes, int n_in,
                              void* d_out, int out_size) {
    const float* x    = (const float*)d_in[0];
    const float* H    = (const float*)d_in[1];
    const float* init = (const float*)d_in[2];
    const float* Wa   = (const float*)d_in[3];
    const float* Ua   = (const float*)d_in[4];
    const float* v    = (const float*)d_in[5];
    const float* Wi   = (const float*)d_in[6];
    const float* Ui   = (const float*)d_in[7];
    const float* Ci   = (const float*)d_in[8];
    const float* bi   = (const float*)d_in[9];
    const float* Wf   = (const float*)d_in[10];
    const float* Uf   = (const float*)d_in[11];
    const float* Cf   = (const float*)d_in[12];
    const float* bf   = (const float*)d_in[13];
    const float* Wc   = (const float*)d_in[14];
    const float* Uc   = (const float*)d_in[15];
    const float* Cc   = (const float*)d_in[16];
    const float* bc   = (const float*)d_in[17];
    const float* Wo   = (const float*)d_in[18];
    const float* Uo   = (const float*)d_in[19];
    const float* Co   = (const float*)d_in[20];
    const float* bo   = (const float*)d_in[21];
    float* out = (float*)d_out;

    hu_kernel<<<(BB * SS) / 8, DD>>>(H, Ua);
    xw_kernel<<<(BB * TT) / 8, 512>>>(x, Wi, Wf, Wc, Wo, bi, bf, bc, bo);
    rec_kernel<<<BB, 1024>>>(H, init, Wa, v, Ui, Ci, Uf, Cf, Uc, Cc, Uo, Co, out);
}

// round 4
// speedup vs baseline: 2.3084x; 2.3084x over previous
#include <cuda_runtime.h>
#include <cuda_bf16.h>
#include <cstdint>

// Problem constants
#define BB 8
#define TT 128
#define SS 512
#define DD 128
#define CLUSTER 4
#define SSLICE (SS / CLUSTER)   // 128 encoder rows per rank
#define NTHR 512
#define NWARP 16

// Scratch (allocation-free rule: __device__ globals)
__device__ float g_HU[BB * SS * DD];   // H @ Ua, [B,S,D]
__device__ float g_XG[BB * TT * 512];  // x@W + bias for 4 gates (i,f,c,o), [B,T,512]

__device__ __forceinline__ float tanh_ap(float x) {
    float y;
    asm("tanh.approx.f32 %0, %1;" : "=f"(y) : "f"(x));
    return y;
}
__device__ __forceinline__ float4 ldg4(const float* p) {
    return __ldg(reinterpret_cast<const float4*>(p));
}
__device__ __forceinline__ uint32_t smem_u32(const void* p) {
    uint32_t a;
    asm("{ .reg .u64 t; cvta.to.shared.u64 t, %1; cvt.u32.u64 %0, t; }" : "=r"(a) : "l"(p));
    return a;
}
// Store a float into the SAME smem offset on cluster CTA `rank`.
__device__ __forceinline__ void st_remote(uint32_t laddr, uint32_t rank, float v) {
    uint32_t ra;
    asm volatile("mapa.shared::cluster.u32 %0, %1, %2;" : "=r"(ra) : "r"(laddr), "r"(rank));
    asm volatile("st.shared::cluster.f32 [%0], %1;" :: "r"(ra), "f"(v) : "memory");
}
#define CLUSTER_SYNC() do { \
    asm volatile("barrier.cluster.arrive.aligned;" ::: "memory"); \
    asm volatile("barrier.cluster.wait.aligned;"   ::: "memory"); \
} while (0)

// ---------------------------------------------------------------------------
// Precompute HU[b,s,e] = sum_d H[b,s,d] * Ua[d,e]
// ---------------------------------------------------------------------------
__global__ void hu_kernel(const float* __restrict__ H, const float* __restrict__ Ua) {
    __shared__ __align__(16) float sH[8][DD];
    const int tid = threadIdx.x;
    const int row0 = blockIdx.x * 8;
    #pragma unroll
    for (int r = 0; r < 8; r++) sH[r][tid] = H[(row0 + r) * DD + tid];
    __syncthreads();

    float acc[8];
    #pragma unroll
    for (int r = 0; r < 8; r++) acc[r] = 0.f;
    #pragma unroll 4
    for (int k = 0; k < DD; k++) {
        float ua = __ldg(Ua + k * DD + tid);
        #pragma unroll
        for (int r = 0; r < 8; r++) acc[r] += sH[r][k] * ua;
    }
    #pragma unroll
    for (int r = 0; r < 8; r++) g_HU[(row0 + r) * DD + tid] = acc[r];
}

// ---------------------------------------------------------------------------
// Precompute XG[row, g*128+jj] = b_g[jj] + sum_k x[row,k] * W_g[k,jj]
// ---------------------------------------------------------------------------
__global__ void xw_kernel(const float* __restrict__ x,
                          const float* __restrict__ Wi, const float* __restrict__ Wf,
                          const float* __restrict__ Wc, const float* __restrict__ Wo,
                          const float* __restrict__ bi, const float* __restrict__ bf,
                          const float* __restrict__ bc, const float* __restrict__ bo) {
    __shared__ __align__(16) float sx[8][DD];
    const int tid = threadIdx.x;
    const int row0 = blockIdx.x * 8;

    for (int i = tid; i < 8 * DD; i += 512)
        sx[i >> 7][i & 127] = x[row0 * DD + i];
    __syncthreads();

    const int g  = tid >> 7;
    const int jj = tid & 127;
    const float* W  = (g == 0) ? Wi : (g == 1) ? Wf : (g == 2) ? Wc : Wo;
    const float* bb = (g == 0) ? bi : (g == 1) ? bf : (g == 2) ? bc : bo;

    float acc[8];
    const float bias = __ldg(bb + jj);
    #pragma unroll
    for (int r = 0; r < 8; r++) acc[r] = bias;
    #pragma unroll 4
    for (int k = 0; k < DD; k++) {
        float w = __ldg(W + k * DD + jj);
        #pragma unroll
        for (int r = 0; r < 8; r++) acc[r] += sx[r][k] * w;
    }
    #pragma unroll
    for (int r = 0; r < 8; r++) g_XG[(row0 + r) * 512 + tid] = acc[r];
}

// ---------------------------------------------------------------------------
// Recurrent kernel: cluster of 4 CTAs per batch. Rank r:
//   - attention over encoder rows [128r, 128r+128)  (HU, H slices in smem)
//   - gate r of the LSTM (U_r, C_r cached in registers)
// Two DSMEM exchanges + 2 cluster syncs per step.
// ---------------------------------------------------------------------------
// dynamic smem layout (floats):
//   sHU   [0      , 16384)   HU slice
//   sH    [16384  , 32768)   H slice
//   sWaT  [32768  , 49152)   Wa transposed: sWaT[j*128+k] = Wa[k*128+j]
//   sh    [49152  , 49280)
//   scell [49280  , 49408)
//   sq    [49408  , 49536)
//   sctx  [49536  , 49664)
//   part  [49664  , 51712)   16 x 128 ctx warp partials
//   zred  [51712  , 51728)   16 warp z partials
//   ctxbuf[51728  , 52240)   4 x 128  (DSMEM mailboxes)
//   zbuf  [52240  , 52244)
//   gbuf  [52244  , 52756)   4 x 128
#define SM_FLOATS 52756

__global__ __launch_bounds__(NTHR, 1) __cluster_dims__(CLUSTER, 1, 1)
void rec_kernel(const float* __restrict__ H, const float* __restrict__ init,
                const float* __restrict__ Wa, const float* __restrict__ v,
                const float* __restrict__ Ui, const float* __restrict__ Ci,
                const float* __restrict__ Uf, const float* __restrict__ Cf,
                const float* __restrict__ Uc, const float* __restrict__ Cc,
                const float* __restrict__ Uo, const float* __restrict__ Co,
                float* __restrict__ out) {
    extern __shared__ __align__(16) float dsm[];
    float* sHU    = dsm;
    float* sHs    = dsm + 16384;
    float* sWaT   = dsm + 32768;
    float* sh     = dsm + 49152;
    float* scell  = dsm + 49280;
    float* sq     = dsm + 49408;
    float* sctx   = dsm + 49536;
    float* part   = dsm + 49664;
    float* zred   = dsm + 51712;
    float* ctxbuf = dsm + 51728;
    float* zbuf   = dsm + 52240;
    float* gbuf   = dsm + 52244;

    const int tid  = threadIdx.x;
    const int lane = tid & 31;
    const int wp   = tid >> 5;
    const int b    = blockIdx.x >> 2;   // batch
    const int rk   = blockIdx.x & 3;    // cluster rank == gate id (i,f,c,o)

    // ---------------- prologue: fill smem ----------------
    {
        const float4* HUsrc = (const float4*)(g_HU + (size_t)(b * SS + rk * SSLICE) * DD);
        const float4* Hsrc  = (const float4*)(H    + (size_t)(b * SS + rk * SSLICE) * DD);
        float4* dHU = (float4*)sHU;
        float4* dH  = (float4*)sHs;
        for (int i = tid; i < SSLICE * DD / 4; i += NTHR) {
            dHU[i] = HUsrc[i];
            dH[i]  = Hsrc[i];
        }
        for (int i = tid; i < DD * DD; i += NTHR) {
            int k = i >> 7, j = i & 127;
            sWaT[j * DD + k] = Wa[i];
        }
        if (tid < DD) {
            sh[tid]    = init[b * DD + tid];
            scell[tid] = init[BB * DD + b * DD + tid];
        }
    }

    // v cached per-lane (float4 of 4 consecutive d)
    const float4 vreg = ldg4(v + 4 * lane);

    // gate-phase constants: column j, k-part p, k = 4*kk + p
    const int gj = (wp << 3) + (lane & 7);   // 0..127 within this gate
    const int gp = lane >> 3;                // 0..3
    const float* Ug = (rk == 0) ? Ui : (rk == 1) ? Uf : (rk == 2) ? Uc : Uo;
    const float* Cg = (rk == 0) ? Ci : (rk == 1) ? Cf : (rk == 2) ? Cc : Co;
    float Ureg[32], Creg[32];
    #pragma unroll
    for (int kk = 0; kk < 32; kk++) {
        const int k = 4 * kk + gp;
        Ureg[kk] = __ldg(Ug + k * DD + gj);
        Creg[kk] = __ldg(Cg + k * DD + gj);
    }

    const float* XGb = g_XG + (size_t)b * TT * 512;

    // DSMEM mailbox local addresses (same offsets on every rank)
    const uint32_t ctx_addr = (tid < DD) ? smem_u32(&ctxbuf[rk * DD + tid]) : 0u;
    const uint32_t z_addr   = smem_u32(&zbuf[rk]);
    const uint32_t g_addr   = smem_u32(&gbuf[rk * DD + gj]);

    __syncthreads();

    for (int t = 0; t < TT; t++) {
        // ---------- P1: q = h @ Wa  (warp w -> outputs [8w, 8w+8)) ----------
        {
            float hreg[4];
            #pragma unroll
            for (int m = 0; m < 4; m++) hreg[m] = sh[32 * m + lane];
            #pragma unroll
            for (int jj = 0; jj < 8; jj++) {
                const float* wt = &sWaT[(wp * 8 + jj) * DD];
                float a = 0.f;
                #pragma unroll
                for (int m = 0; m < 4; m++) a += hreg[m] * wt[32 * m + lane];
                #pragma unroll
                for (int o = 16; o > 0; o >>= 1) a += __shfl_xor_sync(0xffffffffu, a, o);
                if (lane == 0) sq[wp * 8 + jj] = a;
            }
        }
        __syncthreads();  // A

        // ---------- P2+P3 fused: scores -> exp -> ctx partial (no max needed;
        // |score| <= sum|v| ~ 5, exp is safe) ----------
        {
            const float4 q4 = *reinterpret_cast<const float4*>(&sq[lane * 4]);
            float4 ctx4 = make_float4(0.f, 0.f, 0.f, 0.f);
            float zp = 0.f;
            #pragma unroll
            for (int ssx = 0; ssx < 8; ssx++) {
                const int s = 8 * wp + ssx;
                float4 hu = *reinterpret_cast<const float4*>(&sHU[s * DD + lane * 4]);
                float sc = tanh_ap(hu.x + q4.x) * vreg.x
                         + tanh_ap(hu.y + q4.y) * vreg.y
                         + tanh_ap(hu.z + q4.z) * vreg.z
                         + tanh_ap(hu.w + q4.w) * vreg.w;
                #pragma unroll
                for (int o = 16; o > 0; o >>= 1) sc += __shfl_xor_sync(0xffffffffu, sc, o);
                const float e = __expf(sc);   // all lanes hold e
                zp += e;
                float4 h4 = *reinterpret_cast<const float4*>(&sHs[s * DD + lane * 4]);
                ctx4.x += e * h4.x; ctx4.y += e * h4.y;
                ctx4.z += e * h4.z; ctx4.w += e * h4.w;
            }
            *reinterpret_cast<float4*>(&part[wp * DD + lane * 4]) = ctx4;
            if (lane == 0) zred[wp] = zp;
        }
        __syncthreads();  // B

        // ---------- exchange 1: (ctx_r, z_r) -> all ranks ----------
        if (tid < DD) {
            float c = 0.f;
            #pragma unroll
            for (int w = 0; w < NWARP; w++) c += part[w * DD + tid];
            #pragma unroll
            for (int q = 0; q < CLUSTER; q++) st_remote(ctx_addr, q, c);
        }
        if (tid == 0) {
            float z = 0.f;
            #pragma unroll
            for (int w = 0; w < NWARP; w++) z += zred[w];
            #pragma unroll
            for (int q = 0; q < CLUSTER; q++) st_remote(z_addr, q, z);
        }
        CLUSTER_SYNC();   // 1

        // ---------- combine: ctx = sum_r ctx_r / sum_r z_r ----------
        if (tid < DD) {
            const float Z = zbuf[0] + zbuf[1] + zbuf[2] + zbuf[3];
            const float c = ctxbuf[tid] + ctxbuf[DD + tid]
                          + ctxbuf[2 * DD + tid] + ctxbuf[3 * DD + tid];
            sctx[tid] = c / Z;
        }
        __syncthreads();  // C

        // ---------- P4: gate rk, column gj ----------
        {
            float acc = 0.f;
            #pragma unroll
            for (int kk = 0; kk < 32; kk++) {
                const int k = 4 * kk + gp;
                acc += sh[k] * Ureg[kk] + sctx[k] * Creg[kk];
            }
            acc += __shfl_xor_sync(0xffffffffu, acc, 8);
            acc += __shfl_xor_sync(0xffffffffu, acc, 16);
            const float pre = acc + __ldg(XGb + t * 512 + rk * DD + gj);
            const float act = (rk == 2) ? tanhf(pre) : 1.f / (1.f + __expf(-pre));
            // lane with part p ships this gate value to rank p's mailbox
            st_remote(g_addr, (uint32_t)gp, act);
        }
        CLUSTER_SYNC();   // 2

        // ---------- LSTM update (duplicated on every rank) ----------
        if (tid < DD) {
            const float ig = gbuf[tid];
            const float fg = gbuf[DD + tid];
            const float gw = gbuf[2 * DD + tid];
            const float og = gbuf[3 * DD + tid];
            const float cn = fg * scell[tid] + ig * gw;
            const float hn = og * tanhf(cn);
            scell[tid] = cn;
            sh[tid]    = hn;
            if (rk == 0) out[(size_t)(b * TT + t) * DD + tid] = hn;
        }
        __syncthreads();  // D
    }
}

// ---------------------------------------------------------------------------
extern "C" void kernel_launch(void* const* d_in, const int* in_sizes, int n_in,
                              void* d_out, int out_size) {
    const float* x    = (const float*)d_in[0];
    const float* H    = (const float*)d_in[1];
    const float* init = (const float*)d_in[2];
    const float* Wa   = (const float*)d_in[3];
    const float* Ua   = (const float*)d_in[4];
    const float* v    = (const float*)d_in[5];
    const float* Wi   = (const float*)d_in[6];
    const float* Ui   = (const float*)d_in[7];
    const float* Ci   = (const float*)d_in[8];
    const float* bi   = (const float*)d_in[9];
    const float* Wf   = (const float*)d_in[10];
    const float* Uf   = (const float*)d_in[11];
    const float* Cf   = (const float*)d_in[12];
    const float* bf   = (const float*)d_in[13];
    const float* Wc   = (const float*)d_in[14];
    const float* Uc   = (const float*)d_in[15];
    const float* Cc   = (const float*)d_in[16];
    const float* bc   = (const float*)d_in[17];
    const float* Wo   = (const float*)d_in[18];
    const float* Uo   = (const float*)d_in[19];
    const float* Co   = (const float*)d_in[20];
    const float* bo   = (const float*)d_in[21];
    float* out = (float*)d_out;

    static bool attr_set = false;
    if (!attr_set) {
        cudaFuncSetAttribute(rec_kernel,
                             cudaFuncAttributeMaxDynamicSharedMemorySize,
                             SM_FLOATS * sizeof(float));
        attr_set = true;
    }

    hu_kernel<<<(BB * SS) / 8, DD>>>(H, Ua);
    xw_kernel<<<(BB * TT) / 8, 512>>>(x, Wi, Wf, Wc, Wo, bi, bf, bc, bo);
    rec_kernel<<<BB * CLUSTER, NTHR, SM_FLOATS * sizeof(float)>>>(
        H, init, Wa, v, Ui, Ci, Uf, Cf, Uc, Cc, Uo, Co, out);
}

// round 5
// speedup vs baseline: 4.0460x; 1.7527x over previous
#include <cuda_runtime.h>
#include <cuda_bf16.h>
#include <cstdint>

// Problem constants
#define BB 8
#define TT 128
#define SS 512
#define DD 128
#define CLUSTER 8
#define SSLICE (SS / CLUSTER)   // 64 encoder rows per rank
#define NTHR 512
#define NWARP 16

// Scratch (allocation-free rule: __device__ globals)
__device__ float g_HU[BB * SS * DD];   // H @ Ua, [B,S,D]
__device__ float g_XG[BB * TT * 512];  // x@W + bias for 4 gates (i,f,c,o), [B,T,512]

__device__ __forceinline__ float tanh_ap(float x) {
    float y;
    asm("tanh.approx.f32 %0, %1;" : "=f"(y) : "f"(x));
    return y;
}
__device__ __forceinline__ float4 ldg4(const float* p) {
    return __ldg(reinterpret_cast<const float4*>(p));
}
__device__ __forceinline__ uint32_t smem_u32(const void* p) {
    uint32_t a;
    asm("{ .reg .u64 t; cvta.to.shared.u64 t, %1; cvt.u32.u64 %0, t; }" : "=r"(a) : "l"(p));
    return a;
}
// st.async a float to the SAME smem offset on cluster CTA `rank`, completing
// tx bytes on that rank's mbarrier (remote-shared-memory async store).
__device__ __forceinline__ void st_async_remote(uint32_t laddr, uint32_t lmbar,
                                                uint32_t rank, float v) {
    uint32_t ra, rb;
    asm volatile("mapa.shared::cluster.u32 %0, %1, %2;" : "=r"(ra) : "r"(laddr), "r"(rank));
    asm volatile("mapa.shared::cluster.u32 %0, %1, %2;" : "=r"(rb) : "r"(lmbar), "r"(rank));
    asm volatile("st.async.shared::cluster.mbarrier::complete_tx::bytes.b32 [%0], %1, [%2];"
                 :: "r"(ra), "r"(__float_as_uint(v)), "r"(rb) : "memory");
}
__device__ __forceinline__ void mbar_init(uint32_t addr, uint32_t count) {
    asm volatile("mbarrier.init.shared.b64 [%0], %1;" :: "r"(addr), "r"(count) : "memory");
}
__device__ __forceinline__ void mbar_expect_tx(uint32_t addr, uint32_t bytes) {
    asm volatile("mbarrier.arrive.expect_tx.shared.b64 _, [%0], %1;"
                 :: "r"(addr), "r"(bytes) : "memory");
}
__device__ __forceinline__ void mbar_wait(uint32_t addr, uint32_t parity) {
    uint32_t done;
    asm volatile(
        "{\n\t.reg .pred p;\n\t"
        "mbarrier.try_wait.parity.acquire.cta.shared::cta.b64 p, [%1], %2;\n\t"
        "selp.b32 %0, 1, 0, p;\n\t}"
        : "=r"(done) : "r"(addr), "r"(parity) : "memory");
    if (!done) {
        asm volatile(
            "{\n\t.reg .pred P1;\n\t"
            "WL_%=:\n\t"
            "mbarrier.try_wait.parity.acquire.cta.shared::cta.b64 P1, [%0], %1, 0x989680;\n\t"
            "@P1 bra.uni WD_%=;\n\t"
            "bra.uni WL_%=;\n\t"
            "WD_%=:\n\t}"
            :: "r"(addr), "r"(parity) : "memory");
    }
}
#define CLUSTER_SYNC() do { \
    asm volatile("barrier.cluster.arrive.aligned;" ::: "memory"); \
    asm volatile("barrier.cluster.wait.aligned;"   ::: "memory"); \
} while (0)

// ---------------------------------------------------------------------------
// Precompute HU[b,s,e] = sum_d H[b,s,d] * Ua[d,e] ; 16 rows per block
// ---------------------------------------------------------------------------
__global__ void hu_kernel(const float* __restrict__ H, const float* __restrict__ Ua) {
    __shared__ __align__(16) float sH[16][DD];
    const int tid = threadIdx.x;
    const int row0 = blockIdx.x * 16;
    #pragma unroll
    for (int r = 0; r < 16; r++) sH[r][tid] = H[(row0 + r) * DD + tid];
    __syncthreads();

    float acc[16];
    #pragma unroll
    for (int r = 0; r < 16; r++) acc[r] = 0.f;
    #pragma unroll 8
    for (int k = 0; k < DD; k++) {
        float ua = __ldg(Ua + k * DD + tid);
        #pragma unroll
        for (int r = 0; r < 16; r++) acc[r] += sH[r][k] * ua;
    }
    #pragma unroll
    for (int r = 0; r < 16; r++) g_HU[(row0 + r) * DD + tid] = acc[r];
}

// ---------------------------------------------------------------------------
// Precompute XG[row, g*128+jj] = b_g[jj] + sum_k x[row,k] * W_g[k,jj]
// ---------------------------------------------------------------------------
__global__ void xw_kernel(const float* __restrict__ x,
                          const float* __restrict__ Wi, const float* __restrict__ Wf,
                          const float* __restrict__ Wc, const float* __restrict__ Wo,
                          const float* __restrict__ bi, const float* __restrict__ bf,
                          const float* __restrict__ bc, const float* __restrict__ bo) {
    __shared__ __align__(16) float sx[8][DD];
    const int tid = threadIdx.x;
    const int row0 = blockIdx.x * 8;

    for (int i = tid; i < 8 * DD; i += 512)
        sx[i >> 7][i & 127] = x[row0 * DD + i];
    __syncthreads();

    const int g  = tid >> 7;
    const int jj = tid & 127;
    const float* W  = (g == 0) ? Wi : (g == 1) ? Wf : (g == 2) ? Wc : Wo;
    const float* bb = (g == 0) ? bi : (g == 1) ? bf : (g == 2) ? bc : bo;

    float acc[8];
    const float bias = __ldg(bb + jj);
    #pragma unroll
    for (int r = 0; r < 8; r++) acc[r] = bias;
    #pragma unroll 4
    for (int k = 0; k < DD; k++) {
        float w = __ldg(W + k * DD + jj);
        #pragma unroll
        for (int r = 0; r < 8; r++) acc[r] += sx[r][k] * w;
    }
    #pragma unroll
    for (int r = 0; r < 8; r++) g_XG[(row0 + r) * 512 + tid] = acc[r];
}

// ---------------------------------------------------------------------------
// Recurrent kernel: cluster of 8 CTAs per batch. Rank r:
//   - attention over encoder rows [64r, 64r+64)  (HU, H slices in smem)
//   - gate (r>>1), columns [(r&1)*64, (r&1)*64+64)  (U, C cached in registers)
// Exchanges via st.async + mbarrier (no barrier.cluster in the loop).
// ---------------------------------------------------------------------------
// dynamic smem layout (floats):
//   sHU   [0     ,  8192)   HU slice (64 x 128)
//   sH    [8192  , 16384)   H slice
//   sh    [16384 , 16512)
//   scell [16512 , 16640)
//   sq    [16640 , 16768)
//   sctx  [16768 , 16896)
//   part  [16896 , 18944)   16 x 128 ctx warp partials
//   zred  [18944 , 18960)
//   ctxbuf[18960 , 20016)   8 x 132 mailbox (ctx[128] + z at [128])
//   gbuf  [20016 , 20528)   4 x 128 gate mailbox
//   mbars [20528 , 20532)   2 x u64 (ctx, gate)
#define SM_FLOATS 20532

__global__ __launch_bounds__(NTHR, 1) __cluster_dims__(CLUSTER, 1, 1)
void rec_kernel(const float* __restrict__ H, const float* __restrict__ init,
                const float* __restrict__ Wa, const float* __restrict__ v,
                const float* __restrict__ Ui, const float* __restrict__ Ci,
                const float* __restrict__ Uf, const float* __restrict__ Cf,
                const float* __restrict__ Uc, const float* __restrict__ Cc,
                const float* __restrict__ Uo, const float* __restrict__ Co,
                float* __restrict__ out) {
    extern __shared__ __align__(16) float dsm[];
    float* sHU    = dsm;
    float* sHs    = dsm + 8192;
    float* sh     = dsm + 16384;
    float* scell  = dsm + 16512;
    float* sq     = dsm + 16640;
    float* sctx   = dsm + 16768;
    float* part   = dsm + 16896;
    float* zred   = dsm + 18944;
    float* ctxbuf = dsm + 18960;
    float* gbuf   = dsm + 20016;
    float* mbars  = dsm + 20528;

    const int tid  = threadIdx.x;
    const int lane = tid & 31;
    const int wp   = tid >> 5;
    const int b    = blockIdx.x >> 3;   // batch
    const int rk   = blockIdx.x & 7;    // cluster rank

    const uint32_t ctx_mbar  = smem_u32(&mbars[0]);
    const uint32_t gate_mbar = smem_u32(&mbars[2]);

    // ---------------- prologue ----------------
    if (tid == 0) {
        mbar_init(ctx_mbar, 1);
        mbar_init(gate_mbar, 1);
        asm volatile("fence.mbarrier_init.release.cluster;" ::: "memory");
    }
    {
        const float4* HUsrc = (const float4*)(g_HU + (size_t)(b * SS + rk * SSLICE) * DD);
        const float4* Hsrc  = (const float4*)(H    + (size_t)(b * SS + rk * SSLICE) * DD);
        float4* dHU = (float4*)sHU;
        float4* dH  = (float4*)sHs;
        #pragma unroll
        for (int i = 0; i < 4; i++) {
            dHU[tid + i * NTHR] = HUsrc[tid + i * NTHR];
            dH[tid + i * NTHR]  = Hsrc[tid + i * NTHR];
        }
        if (tid < DD) {
            sh[tid]    = init[b * DD + tid];
            scell[tid] = init[BB * DD + b * DD + tid];
        }
    }

    // v cached per-lane (float4 of 4 consecutive d)
    const float4 vreg = ldg4(v + 4 * lane);

    // P1 layout: warp wp -> q cols [8wp, 8wp+8); col = 8wp + (lane&7),
    // k-part p = lane>>3 (4 parts), k = p + 4*kk. Wa cached in registers.
    const int qcol = (wp << 3) + (lane & 7);
    const int qp   = lane >> 3;
    float waReg[32];
    #pragma unroll
    for (int kk = 0; kk < 32; kk++)
        waReg[kk] = __ldg(Wa + (qp + 4 * kk) * DD + qcol);

    // P4 layout: gate = rk>>1, columns gc0 + [0,64).
    // thread: col = tid>>3 (0..63), part p = tid&7, k = p + 8*kk (16 k each).
    const int gate = rk >> 1;
    const int gc0  = (rk & 1) * 64;
    const int gcol = gc0 + (tid >> 3);
    const int gp   = tid & 7;
    const float* Ug = (gate == 0) ? Ui : (gate == 1) ? Uf : (gate == 2) ? Uc : Uo;
    const float* Cg = (gate == 0) ? Ci : (gate == 1) ? Cf : (gate == 2) ? Cc : Co;
    float Ureg[16], Creg[16];
    #pragma unroll
    for (int kk = 0; kk < 16; kk++) {
        const int k = gp + 8 * kk;
        Ureg[kk] = __ldg(Ug + k * DD + gcol);
        Creg[kk] = __ldg(Cg + k * DD + gcol);
    }

    const float* XGb = g_XG + (size_t)b * TT * 512;

    // Local mailbox slot addresses (same offsets on all ranks; sender-indexed)
    const uint32_t ctx_addr = (tid < DD) ? smem_u32(&ctxbuf[rk * 132 + tid]) : 0u;
    const uint32_t zsl_addr = smem_u32(&ctxbuf[rk * 132 + 128]);
    const uint32_t g_addr   = smem_u32(&gbuf[gate * DD + gcol]);

    __syncthreads();
    CLUSTER_SYNC();   // mbarriers + smem ready on every rank

    for (int t = 0; t < TT; t++) {
        const uint32_t parity = (uint32_t)(t & 1);
        // register expected tx for this step early (negative-tx transients are OK,
        // but early registration keeps the fast path)
        if (tid == 0) {
            mbar_expect_tx(ctx_mbar,  CLUSTER * 129 * 4);
            mbar_expect_tx(gate_mbar, 512 * 4);
        }
        // prefetch this step's x-gate contribution
        const float xg = __ldg(XGb + t * 512 + gate * DD + gcol);

        // ---------- P1: q = h @ Wa (Wa in registers) ----------
        {
            float acc = 0.f;
            #pragma unroll
            for (int kk = 0; kk < 32; kk++)
                acc += sh[qp + 4 * kk] * waReg[kk];
            acc += __shfl_xor_sync(0xffffffffu, acc, 8);
            acc += __shfl_xor_sync(0xffffffffu, acc, 16);
            if (lane < 8) sq[(wp << 3) + lane] = acc;
        }
        __syncthreads();  // A

        // ---------- P2: scores -> exp -> ctx partial (fused; no-max softmax:
        // |score| <= sum|v| ~ 5, exp is safe) ----------
        {
            const float4 q4 = *reinterpret_cast<const float4*>(&sq[lane * 4]);
            float4 ctx4 = make_float4(0.f, 0.f, 0.f, 0.f);
            float zp = 0.f;
            #pragma unroll
            for (int ssx = 0; ssx < 4; ssx++) {
                const int s = wp + (ssx << 4);     // 0..63
                float4 hu = *reinterpret_cast<const float4*>(&sHU[s * DD + lane * 4]);
                float sc = tanh_ap(hu.x + q4.x) * vreg.x
                         + tanh_ap(hu.y + q4.y) * vreg.y
                         + tanh_ap(hu.z + q4.z) * vreg.z
                         + tanh_ap(hu.w + q4.w) * vreg.w;
                #pragma unroll
                for (int o = 16; o > 0; o >>= 1) sc += __shfl_xor_sync(0xffffffffu, sc, o);
                const float e = __expf(sc);        // all lanes hold e
                zp += e;
                float4 h4 = *reinterpret_cast<const float4*>(&sHs[s * DD + lane * 4]);
                ctx4.x += e * h4.x; ctx4.y += e * h4.y;
                ctx4.z += e * h4.z; ctx4.w += e * h4.w;
            }
            *reinterpret_cast<float4*>(&part[wp * DD + lane * 4]) = ctx4;
            if (lane == 0) zred[wp] = zp;
        }
        __syncthreads();  // B

        // ---------- exchange 1: (ctx_r, z_r) -> all ranks via st.async ----------
        if (tid < DD) {
            float c = 0.f;
            #pragma unroll
            for (int w = 0; w < NWARP; w++) c += part[w * DD + tid];
            #pragma unroll
            for (int q = 0; q < CLUSTER; q++)
                st_async_remote(ctx_addr, ctx_mbar, (uint32_t)q, c);
        } else if (tid == DD) {
            float z = 0.f;
            #pragma unroll
            for (int w = 0; w < NWARP; w++) z += zred[w];
            #pragma unroll
            for (int q = 0; q < CLUSTER; q++)
                st_async_remote(zsl_addr, ctx_mbar, (uint32_t)q, z);
        }
        mbar_wait(ctx_mbar, parity);

        // ---------- combine: ctx = sum_r ctx_r / sum_r z_r ----------
        if (tid < DD) {
            float Z = 0.f, c = 0.f;
            #pragma unroll
            for (int q = 0; q < CLUSTER; q++) {
                Z += ctxbuf[q * 132 + 128];
                c += ctxbuf[q * 132 + tid];
            }
            sctx[tid] = c / Z;
        }
        __syncthreads();  // C

        // ---------- P4: gate slice (U, C in registers) ----------
        {
            float acc = 0.f;
            #pragma unroll
            for (int kk = 0; kk < 16; kk++) {
                const int k = gp + 8 * kk;
                acc += sh[k] * Ureg[kk] + sctx[k] * Creg[kk];
            }
            acc += __shfl_xor_sync(0xffffffffu, acc, 1);
            acc += __shfl_xor_sync(0xffffffffu, acc, 2);
            acc += __shfl_xor_sync(0xffffffffu, acc, 4);
            const float pre = acc + xg;
            const float act = (gate == 2) ? tanhf(pre) : 1.f / (1.f + __expf(-pre));
            // lane with part p ships this gate value to rank p's mailbox
            st_async_remote(g_addr, gate_mbar, (uint32_t)gp, act);
        }
        mbar_wait(gate_mbar, parity);

        // ---------- LSTM update (duplicated on every rank) ----------
        if (tid < DD) {
            const float ig = gbuf[tid];
            const float fg = gbuf[DD + tid];
            const float gw = gbuf[2 * DD + tid];
            const float og = gbuf[3 * DD + tid];
            const float cn = fg * scell[tid] + ig * gw;
            const float hn = og * tanhf(cn);
            scell[tid] = cn;
            sh[tid]    = hn;
            if (rk == 0) out[(size_t)(b * TT + t) * DD + tid] = hn;
        }
        __syncthreads();  // D
    }
}

// ---------------------------------------------------------------------------
extern "C" void kernel_launch(void* const* d_in, const int* in_sizes, int n_in,
                              void* d_out, int out_size) {
    const float* x    = (const float*)d_in[0];
    const float* H    = (const float*)d_in[1];
    const float* init = (const float*)d_in[2];
    const float* Wa   = (const float*)d_in[3];
    const float* Ua   = (const float*)d_in[4];
    const float* v    = (const float*)d_in[5];
    const float* Wi   = (const float*)d_in[6];
    const float* Ui   = (const float*)d_in[7];
    const float* Ci   = (const float*)d_in[8];
    const float* bi   = (const float*)d_in[9];
    const float* Wf   = (const float*)d_in[10];
    const float* Uf   = (const float*)d_in[11];
    const float* Cf   = (const float*)d_in[12];
    const float* bf   = (const float*)d_in[13];
    const float* Wc   = (const float*)d_in[14];
    const float* Uc   = (const float*)d_in[15];
    const float* Cc   = (const float*)d_in[16];
    const float* bc   = (const float*)d_in[17];
    const float* Wo   = (const float*)d_in[18];
    const float* Uo   = (const float*)d_in[19];
    const float* Co   = (const float*)d_in[20];
    const float* bo   = (const float*)d_in[21];
    float* out = (float*)d_out;

    static bool attr_set = false;
    if (!attr_set) {
        cudaFuncSetAttribute(rec_kernel,
                             cudaFuncAttributeMaxDynamicSharedMemorySize,
                             SM_FLOATS * sizeof(float));
        attr_set = true;
    }

    hu_kernel<<<(BB * SS) / 16, DD>>>(H, Ua);
    xw_kernel<<<(BB * TT) / 8, 512>>>(x, Wi, Wf, Wc, Wo, bi, bf, bc, bo);
    rec_kernel<<<BB * CLUSTER, NTHR, SM_FLOATS * sizeof(float)>>>(
        H, init, Wa, v, Ui, Ci, Uf, Cf, Uc, Cc, Uo, Co, out);
}